// round 7
// baseline (speedup 1.0000x reference)
#include <cuda_runtime.h>
#include <cuda_bf16.h>
#include <cstdint>

#define N_GRAPHS 256
#define N_NODES  100000
#define N_EDGES  1000000
#define EMB      64
#define EMB_RBF  16
#define TILE_CTA 64
#define N_TILES  (N_EDGES / TILE_CTA)    // 15625 exactly
#define GRID_MAIN 444

// ---------------- device scratch ----------------
__device__ float        g_M[EMB * EMB_RBF];           // M[j][k], j=feat 0..63, k=0..15
__device__ __align__(32) float g_acc8[N_GRAPHS * 8];  // xx,yy,zz,xy,xz,yz,pad,pad
__device__ unsigned int g_cnt[N_GRAPHS];
__device__ int          g_ei64;

// ---------------- helpers ----------------
__device__ __forceinline__ int load_idx(const void* p, int i, int is64) {
    if (is64) return (int)((const long long*)p)[i];
    return ((const int*)p)[i];
}

// bf16 hi/lo split of two fp32 -> packed bf16x2 (lower half = first value)
__device__ __forceinline__ void split_pack(float f0, float f1, uint32_t& hi, uint32_t& lo) {
    uint32_t h;
    asm("cvt.rn.bf16x2.f32 %0, %1, %2;" : "=r"(h) : "f"(f1), "f"(f0));
    float r0 = f0 - __uint_as_float(h << 16);
    float r1 = f1 - __uint_as_float(h & 0xFFFF0000u);
    uint32_t l;
    asm("cvt.rn.bf16x2.f32 %0, %1, %2;" : "=r"(l) : "f"(r1), "f"(r0));
    hi = h; lo = l;
}

__device__ __forceinline__ void mma_bf16(float* d, const uint32_t* a, uint32_t b0, uint32_t b1) {
    asm volatile(
        "mma.sync.aligned.m16n8k16.row.col.f32.bf16.bf16.f32 "
        "{%0,%1,%2,%3}, {%4,%5,%6,%7}, {%8,%9}, {%0,%1,%2,%3};"
        : "+f"(d[0]), "+f"(d[1]), "+f"(d[2]), "+f"(d[3])
        : "r"(a[0]), "r"(a[1]), "r"(a[2]), "r"(a[3]), "r"(b0), "r"(b1));
}

__device__ __forceinline__ uint32_t movm(uint32_t x) {
    uint32_t y;
    asm("movmatrix.sync.aligned.m8n8.trans.b16 %0, %1;" : "=r"(y) : "r"(x));
    return y;
}

// ---------------- setup: detect + zero + fold M ----------------
__global__ void setup_kernel(const float* __restrict__ W2,
                             const float* __restrict__ Wrbf,
                             const float* __restrict__ Wout,
                             const void*  __restrict__ ei) {
    int t = threadIdx.x;   // 1024
    if (t == 0) {
        const int* p = (const int*)ei;
        int all0 = 1;
        for (int i = 0; i < 64; i++) if (p[2 * i + 1] != 0) { all0 = 0; break; }
        g_ei64 = all0;
    }
    g_acc8[t] = 0.0f;
    g_acc8[t + 1024] = 0.0f;
    if (t < N_GRAPHS) g_cnt[t] = 0u;
    // M[j][k] = sum_m W2[j][m] * Wout[m] * W_rbf[k][m]
    int j = t >> 4, k = t & 15;
    float acc = 0.0f;
    #pragma unroll 8
    for (int m = 0; m < EMB; m++)
        acc += W2[j * EMB + m] * Wout[m] * Wrbf[k * EMB + m];
    g_M[j * EMB_RBF + k] = acc;
}

// ---------------- main fused kernel ----------------
__global__ void __launch_bounds__(128, 3)
main_kernel(const float* __restrict__ edge_emb,
            const void*  __restrict__ edge_index,
            const float* __restrict__ distance_vec,
            const void*  __restrict__ batch,
            const float* __restrict__ rbf,
            const float* __restrict__ W1) {
    __shared__ uint32_t afh[16 * 32 * 4];   // W1^T hi fragments
    __shared__ uint32_t afl[16 * 32 * 4];   // W1^T lo fragments

    const int tid  = threadIdx.x;
    const int wid  = tid >> 5;
    const int lane = tid & 31;
    const int is64 = g_ei64;

    // ---- prologue: A fragments of W1^T (hi/lo) into smem ----
    // A[m][k] = W1[k*64+m]; per (mt,kt,lane): a0:(r0,k0..k0+1) a1:(r0+8) a2:(r0,k0+8) a3:(r0+8,k0+8)
    for (int p = wid; p < 16; p += 4) {
        int mt = p >> 2, kt = p & 3;
        int r0 = 16 * mt + (lane >> 2);
        int r1 = r0 + 8;
        int k0 = 16 * kt + (lane & 3) * 2;
        uint32_t hi[4], lo[4];
        split_pack(W1[(k0    ) * EMB + r0], W1[(k0 + 1) * EMB + r0], hi[0], lo[0]);
        split_pack(W1[(k0    ) * EMB + r1], W1[(k0 + 1) * EMB + r1], hi[1], lo[1]);
        split_pack(W1[(k0 + 8) * EMB + r0], W1[(k0 + 9) * EMB + r0], hi[2], lo[2]);
        split_pack(W1[(k0 + 8) * EMB + r1], W1[(k0 + 9) * EMB + r1], hi[3], lo[3]);
        uint32_t base = (uint32_t)(p * 32 + lane) * 4;
        #pragma unroll
        for (int r = 0; r < 4; r++) { afh[base + r] = hi[r]; afl[base + r] = lo[r]; }
    }

    // ---- stage-2 B fragments (M matrix) -> constant registers ----
    // B(k=feat j, n): M[j][n]; frag (kt,nt): b0 at k=16kt+2(lane%4)+{0,1}, n=8nt+lane/4; b1 at k+8
    uint32_t Bh[4][2][2], Bl[4][2][2];
    {
        int k0 = 2 * (lane & 3);
        int nn = lane >> 2;
        #pragma unroll
        for (int kt = 0; kt < 4; kt++) {
            #pragma unroll
            for (int nt = 0; nt < 2; nt++) {
                int kk = 16 * kt + k0;
                int n  = 8 * nt + nn;
                split_pack(g_M[(kk    ) * EMB_RBF + n], g_M[(kk + 1) * EMB_RBF + n],
                           Bh[kt][nt][0], Bl[kt][nt][0]);
                split_pack(g_M[(kk + 8) * EMB_RBF + n], g_M[(kk + 9) * EMB_RBF + n],
                           Bh[kt][nt][1], Bl[kt][nt][1]);
            }
        }
    }
    __syncthreads();

    const int m4 = lane >> 2;      // 0..7
    const int j4 = lane & 3;       // 0..3

    for (int tile = blockIdx.x; tile < N_TILES; tile += GRID_MAIN) {
        const int base16 = tile * TILE_CTA + wid * 16;   // this warp's 16 edges

        // ---- stage-1 B fragments: E rows, bf16 hi/lo, 2 edge-subgroups ----
        uint32_t bhi[2][8], blo[2][8];
        #pragma unroll
        for (int g = 0; g < 2; g++) {
            int ec = base16 + 8 * g + m4;
            const float2* Ep = (const float2*)(edge_emb + (size_t)ec * EMB);
            #pragma unroll
            for (int kt = 0; kt < 4; kt++) {
                float2 x = Ep[j4 + 8 * kt];
                float2 y = Ep[j4 + 8 * kt + 4];
                split_pack(x.x, x.y, bhi[g][2 * kt], blo[g][2 * kt]);
                split_pack(y.x, y.y, bhi[g][2 * kt + 1], blo[g][2 * kt + 1]);
            }
        }

        // ---- stage-1 MMAs: P = E @ W1, 3-term bf16 split, 16 edges ----
        float d0[16], d1[16];
        #pragma unroll
        for (int i = 0; i < 16; i++) { d0[i] = 0.0f; d1[i] = 0.0f; }

        #pragma unroll
        for (int mt = 0; mt < 4; mt++) {
            #pragma unroll
            for (int kt = 0; kt < 4; kt++) {
                uint4 ah = *(const uint4*)&afh[((mt * 4 + kt) * 32 + lane) * 4];
                uint4 al = *(const uint4*)&afl[((mt * 4 + kt) * 32 + lane) * 4];
                mma_bf16(d0 + mt * 4, &ah.x, bhi[0][2 * kt], bhi[0][2 * kt + 1]);
                mma_bf16(d0 + mt * 4, &al.x, bhi[0][2 * kt], bhi[0][2 * kt + 1]);
                mma_bf16(d0 + mt * 4, &ah.x, blo[0][2 * kt], blo[0][2 * kt + 1]);
                mma_bf16(d1 + mt * 4, &ah.x, bhi[1][2 * kt], bhi[1][2 * kt + 1]);
                mma_bf16(d1 + mt * 4, &al.x, bhi[1][2 * kt], bhi[1][2 * kt + 1]);
                mma_bf16(d1 + mt * 4, &ah.x, blo[1][2 * kt], blo[1][2 * kt + 1]);
            }
        }

        // ---- silu in registers ----
        #pragma unroll
        for (int i = 0; i < 16; i++) {
            float x0 = d0[i];
            d0[i] = __fdividef(x0, 1.0f + __expf(-x0));
            float x1 = d1[i];
            d1[i] = __fdividef(x1, 1.0f + __expf(-x1));
        }

        // ---- register transpose: D-frags -> stage-2 A-frags via movmatrix ----
        // tile(g,mt,hh) = (d[mt*4+2hh], d[mt*4+2hh+1]) : feats 16mt+8hh..+7, edges 8g..+7
        uint32_t mvh[4][2][2], mvl[4][2][2];   // [mt][g][hh]
        #pragma unroll
        for (int mt = 0; mt < 4; mt++) {
            #pragma unroll
            for (int hh = 0; hh < 2; hh++) {
                uint32_t h0, l0, h1, l1;
                split_pack(d0[mt * 4 + 2 * hh], d0[mt * 4 + 2 * hh + 1], h0, l0);
                split_pack(d1[mt * 4 + 2 * hh], d1[mt * 4 + 2 * hh + 1], h1, l1);
                mvh[mt][0][hh] = movm(h0);
                mvl[mt][0][hh] = movm(l0);
                mvh[mt][1][hh] = movm(h1);
                mvl[mt][1][hh] = movm(l1);
            }
        }

        // ---- stage-2 MMAs: q[16e,16] = h @ M, 3-term split ----
        float q0[4], q1[4];
        #pragma unroll
        for (int i = 0; i < 4; i++) { q0[i] = 0.0f; q1[i] = 0.0f; }
        #pragma unroll
        for (int kt = 0; kt < 4; kt++) {
            uint32_t ah[4] = {mvh[kt][0][0], mvh[kt][1][0], mvh[kt][0][1], mvh[kt][1][1]};
            uint32_t al[4] = {mvl[kt][0][0], mvl[kt][1][0], mvl[kt][0][1], mvl[kt][1][1]};
            mma_bf16(q0, ah, Bh[kt][0][0], Bh[kt][0][1]);
            mma_bf16(q0, al, Bh[kt][0][0], Bh[kt][0][1]);
            mma_bf16(q0, ah, Bl[kt][0][0], Bl[kt][0][1]);
            mma_bf16(q1, ah, Bh[kt][1][0], Bh[kt][1][1]);
            mma_bf16(q1, al, Bh[kt][1][0], Bh[kt][1][1]);
            mma_bf16(q1, ah, Bl[kt][1][0], Bl[kt][1][1]);
        }
        // q layout: (edge m4 [+8], n = 8*nt + 2*j4 + {0,1})

        // ---- s = q . rbf  (butterfly over the 4-lane n-groups) ----
        const float2* R0 = (const float2*)(rbf + (size_t)(base16 + m4) * EMB_RBF);
        const float2* R1 = (const float2*)(rbf + (size_t)(base16 + m4 + 8) * EMB_RBF);
        float2 r00 = R0[j4], r01 = R0[4 + j4];
        float2 r10 = R1[j4], r11 = R1[4 + j4];
        float p0 = q0[0] * r00.x + q0[1] * r00.y + q1[0] * r01.x + q1[1] * r01.y;
        float p1 = q0[2] * r10.x + q0[3] * r10.y + q1[2] * r11.x + q1[3] * r11.y;
        p0 += __shfl_xor_sync(0xFFFFFFFFu, p0, 1);
        p0 += __shfl_xor_sync(0xFFFFFFFFu, p0, 2);
        p1 += __shfl_xor_sync(0xFFFFFFFFu, p1, 1);
        p1 += __shfl_xor_sync(0xFFFFFFFFu, p1, 2);

        // ---- geometry + global reduction (lanes j4<2: j4==0 -> edge m4, j4==1 -> edge m4+8) ----
        if (j4 < 2) {
            int e = base16 + m4 + 8 * j4;
            float s = j4 ? p1 : p0;
            int node = load_idx(edge_index, e, is64);
            node = min(max(node, 0), N_NODES - 1);
            int g = load_idx(batch, node, is64);
            g = min(max(g, 0), N_GRAPHS - 1);
            float dx = distance_vec[3 * e + 0];
            float dy = distance_vec[3 * e + 1];
            float dz = distance_vec[3 * e + 2];
            float coef = s * rsqrtf(dx * dx + dy * dy + dz * dz);
            float* ag = g_acc8 + g * 8;
            atomicAdd(ag + 0, coef * dx * dx);
            atomicAdd(ag + 1, coef * dy * dy);
            atomicAdd(ag + 2, coef * dz * dz);
            atomicAdd(ag + 3, coef * dx * dy);
            atomicAdd(ag + 4, coef * dx * dz);
            atomicAdd(ag + 5, coef * dy * dz);
            atomicAdd(&g_cnt[g], 1u);
        }
    }
}

// ---------------- finalize ----------------
__global__ void finalize_kernel(float* __restrict__ out) {
    int g = blockIdx.x * blockDim.x + threadIdx.x;
    if (g >= N_GRAPHS) return;
    unsigned int c = g_cnt[g];
    float inv = c ? (1.0f / (float)c) : 0.0f;
    float xx = g_acc8[g * 8 + 0] * inv;
    float yy = g_acc8[g * 8 + 1] * inv;
    float zz = g_acc8[g * 8 + 2] * inv;
    float xy = g_acc8[g * 8 + 3] * inv;
    float xz = g_acc8[g * 8 + 4] * inv;
    float yz = g_acc8[g * 8 + 5] * inv;
    float* o = out + g * 9;
    o[0] = xx; o[1] = xy; o[2] = xz;
    o[3] = xy; o[4] = yy; o[5] = yz;
    o[6] = xz; o[7] = yz; o[8] = zz;
}

// ---------------- launcher ----------------
extern "C" void kernel_launch(void* const* d_in, const int* in_sizes, int n_in,
                              void* d_out, int out_size) {
    int i_ee = 0, i_ei = 1, i_dv = 2, i_b = 4, i_rbf = 5,
        i_w1 = 6, i_w2 = 7, i_wr = 8, i_wo = 9;
    int seen4096 = 0;
    for (int i = 0; i < n_in; i++) {
        int s = in_sizes[i];
        if      (s == 64000000) i_ee = i;
        else if (s == 2000000)  i_ei = i;
        else if (s == 3000000)  i_dv = i;
        else if (s == 100000)   i_b  = i;
        else if (s == 16000000) i_rbf = i;
        else if (s == 4096)     { if (seen4096++ == 0) i_w1 = i; else i_w2 = i; }
        else if (s == 1024)     i_wr = i;
        else if (s == 64)       i_wo = i;
    }

    const float* edge_emb     = (const float*)d_in[i_ee];
    const void*  edge_index   = d_in[i_ei];
    const float* distance_vec = (const float*)d_in[i_dv];
    const void*  batch        = d_in[i_b];
    const float* rbf          = (const float*)d_in[i_rbf];
    const float* W1           = (const float*)d_in[i_w1];
    const float* W2           = (const float*)d_in[i_w2];
    const float* W_rbf        = (const float*)d_in[i_wr];
    const float* W_out        = (const float*)d_in[i_wo];
    float* out = (float*)d_out;

    setup_kernel<<<1, 1024>>>(W2, W_rbf, W_out, edge_index);
    main_kernel<<<GRID_MAIN, 128>>>(edge_emb, edge_index, distance_vec, batch, rbf, W1);
    finalize_kernel<<<1, 256>>>(out);
    (void)out_size;
}

// round 9
// speedup vs baseline: 3.3023x; 3.3023x over previous
#include <cuda_runtime.h>
#include <cuda_bf16.h>
#include <cstdint>

#define N_GRAPHS 256
#define N_NODES  100000
#define N_EDGES  1000000
#define EMB      64
#define EMB_RBF  16
#define TILE_CTA 128
#define N_TILES  ((N_EDGES + TILE_CTA - 1) / TILE_CTA)  // 7813
#define GRID_MAIN 444

typedef unsigned long long ull;

// ---------------- device scratch ----------------
__device__ float        g_M[EMB * EMB_RBF];    // M[j][k] = sum_m W2[j][m]*Wout[m]*Wrbf[k][m]
__device__ float        g_acc6[N_GRAPHS * 6];
__device__ unsigned int g_cnt[N_GRAPHS];
__device__ int          g_ei64;

// ---------------- helpers ----------------
__device__ __forceinline__ int load_idx(const void* p, int i, int is64) {
    if (is64) return (int)((const long long*)p)[i];
    return ((const int*)p)[i];
}
__device__ __forceinline__ ull pack2u(uint32_t lo, uint32_t hi) {
    ull r; asm("mov.b64 %0, {%1, %2};" : "=l"(r) : "r"(lo), "r"(hi)); return r;
}
__device__ __forceinline__ void unpack2u(ull v, uint32_t& lo, uint32_t& hi) {
    asm("mov.b64 {%0, %1}, %2;" : "=r"(lo), "=r"(hi) : "l"(v));
}

// bf16 hi/lo split of two fp32 -> packed bf16x2 (lower half = first value)
__device__ __forceinline__ void split_pack(float f0, float f1, uint32_t& hi, uint32_t& lo) {
    uint32_t h;
    asm("cvt.rn.bf16x2.f32 %0, %1, %2;" : "=r"(h) : "f"(f1), "f"(f0));
    float r0 = f0 - __uint_as_float(h << 16);
    float r1 = f1 - __uint_as_float(h & 0xFFFF0000u);
    uint32_t l;
    asm("cvt.rn.bf16x2.f32 %0, %1, %2;" : "=r"(l) : "f"(r1), "f"(r0));
    hi = h; lo = l;
}

__device__ __forceinline__ void mma_bf16(float* d, const uint32_t* a, uint32_t b0, uint32_t b1) {
    asm volatile(
        "mma.sync.aligned.m16n8k16.row.col.f32.bf16.bf16.f32 "
        "{%0,%1,%2,%3}, {%4,%5,%6,%7}, {%8,%9}, {%0,%1,%2,%3};"
        : "+f"(d[0]), "+f"(d[1]), "+f"(d[2]), "+f"(d[3])
        : "r"(a[0]), "r"(a[1]), "r"(a[2]), "r"(a[3]), "r"(b0), "r"(b1));
}

__device__ __forceinline__ uint32_t movm(uint32_t x) {
    uint32_t y;
    asm("movmatrix.sync.aligned.m8n8.trans.b16 %0, %1;" : "=r"(y) : "r"(x));
    return y;
}

// ---------------- setup: parallel detect + zero + fold M ----------------
__global__ void setup_kernel(const float* __restrict__ W2,
                             const float* __restrict__ Wrbf,
                             const float* __restrict__ Wout,
                             const void*  __restrict__ ei) {
    __shared__ int nz;
    int t = threadIdx.x;   // 1024
    if (t == 0) nz = 0;
    __syncthreads();
    if (t < 64) {
        if (((const int*)ei)[2 * t + 1] != 0) atomicAdd(&nz, 1);
    }
    for (int i = t; i < N_GRAPHS * 6; i += 1024) g_acc6[i] = 0.0f;
    if (t < N_GRAPHS) g_cnt[t] = 0u;
    int j = t >> 4, k = t & 15;
    float acc = 0.0f;
    #pragma unroll 8
    for (int m = 0; m < EMB; m++)
        acc += W2[j * EMB + m] * Wout[m] * Wrbf[k * EMB + m];
    g_M[j * EMB_RBF + k] = acc;
    __syncthreads();
    if (t == 0) g_ei64 = (nz == 0);
}

// ---------------- main fused kernel ----------------
__global__ void __launch_bounds__(128)
main_kernel(const float* __restrict__ edge_emb,
            const void*  __restrict__ edge_index,
            const float* __restrict__ distance_vec,
            const void*  __restrict__ batch,
            const float* __restrict__ rbf,
            const float* __restrict__ W1) {
    __shared__ uint32_t afh[16 * 32 * 4];     // W1^T hi fragments (8KB)
    __shared__ uint32_t afl[16 * 32 * 4];     // W1^T lo fragments (8KB)
    __shared__ ull      Mfh[8 * 32];          // stage-2 M B-frags hi (b0 lo-word, b1 hi-word)
    __shared__ ull      Mfl[8 * 32];          // stage-2 M B-frags lo
    __shared__ unsigned int sCnt[N_GRAPHS];
    __shared__ float        sAcc[N_GRAPHS * 6];

    const int tid  = threadIdx.x;
    const int wid  = tid >> 5;
    const int lane = tid & 31;
    const int is64 = g_ei64;
    const int m4 = lane >> 2;      // 0..7
    const int j4 = lane & 3;       // 0..3

    // ---- prologue: A fragments of W1^T (hi/lo) into smem ----
    for (int p = wid; p < 16; p += 4) {
        int mt = p >> 2, kt = p & 3;
        int r0 = 16 * mt + m4;
        int r1 = r0 + 8;
        int k0 = 16 * kt + j4 * 2;
        uint32_t hi[4], lo[4];
        split_pack(W1[(k0    ) * EMB + r0], W1[(k0 + 1) * EMB + r0], hi[0], lo[0]);
        split_pack(W1[(k0    ) * EMB + r1], W1[(k0 + 1) * EMB + r1], hi[1], lo[1]);
        split_pack(W1[(k0 + 8) * EMB + r0], W1[(k0 + 9) * EMB + r0], hi[2], lo[2]);
        split_pack(W1[(k0 + 8) * EMB + r1], W1[(k0 + 9) * EMB + r1], hi[3], lo[3]);
        uint32_t base = (uint32_t)(p * 32 + lane) * 4;
        #pragma unroll
        for (int r = 0; r < 4; r++) { afh[base + r] = hi[r]; afl[base + r] = lo[r]; }
    }
    // ---- stage-2 M fragments into smem: (kt,nt) per lane ----
    for (int p = wid; p < 8; p += 4) {
        int kt = p >> 1, nt = p & 1;
        int kk = 16 * kt + 2 * j4;
        int n  = 8 * nt + m4;
        uint32_t b0h, b0l, b1h, b1l;
        split_pack(g_M[(kk    ) * EMB_RBF + n], g_M[(kk + 1) * EMB_RBF + n], b0h, b0l);
        split_pack(g_M[(kk + 8) * EMB_RBF + n], g_M[(kk + 9) * EMB_RBF + n], b1h, b1l);
        Mfh[p * 32 + lane] = pack2u(b0h, b1h);
        Mfl[p * 32 + lane] = pack2u(b0l, b1l);
    }
    for (int i = tid; i < N_GRAPHS; i += 128) sCnt[i] = 0u;
    for (int i = tid; i < N_GRAPHS * 6; i += 128) sAcc[i] = 0.0f;
    __syncthreads();

    for (int tile = blockIdx.x; tile < N_TILES; tile += GRID_MAIN) {
        const int base32 = tile * TILE_CTA + wid * 32;

        #pragma unroll 1
        for (int pair = 0; pair < 2; pair++) {
            const int base16 = base32 + pair * 16;

            // ---- stage-1 B fragments: E rows, bf16 hi/lo, 2 edge-subgroups ----
            uint32_t bhi[2][8], blo[2][8];
            #pragma unroll
            for (int g = 0; g < 2; g++) {
                int ec = min(base16 + 8 * g + m4, N_EDGES - 1);
                const float2* Ep = (const float2*)(edge_emb + (size_t)ec * EMB);
                #pragma unroll
                for (int kt = 0; kt < 4; kt++) {
                    float2 x = Ep[j4 + 8 * kt];
                    float2 y = Ep[j4 + 8 * kt + 4];
                    split_pack(x.x, x.y, bhi[g][2 * kt], blo[g][2 * kt]);
                    split_pack(y.x, y.y, bhi[g][2 * kt + 1], blo[g][2 * kt + 1]);
                }
            }

            // ---- stage-1 MMAs: P = E @ W1, 3-term bf16 split, 16 edges ----
            float d0[16], d1[16];
            #pragma unroll
            for (int i = 0; i < 16; i++) { d0[i] = 0.0f; d1[i] = 0.0f; }
            #pragma unroll
            for (int mt = 0; mt < 4; mt++) {
                #pragma unroll
                for (int kt = 0; kt < 4; kt++) {
                    uint4 ah = *(const uint4*)&afh[((mt * 4 + kt) * 32 + lane) * 4];
                    uint4 al = *(const uint4*)&afl[((mt * 4 + kt) * 32 + lane) * 4];
                    mma_bf16(d0 + mt * 4, &ah.x, bhi[0][2 * kt], bhi[0][2 * kt + 1]);
                    mma_bf16(d0 + mt * 4, &al.x, bhi[0][2 * kt], bhi[0][2 * kt + 1]);
                    mma_bf16(d0 + mt * 4, &ah.x, blo[0][2 * kt], blo[0][2 * kt + 1]);
                    mma_bf16(d1 + mt * 4, &ah.x, bhi[1][2 * kt], bhi[1][2 * kt + 1]);
                    mma_bf16(d1 + mt * 4, &al.x, bhi[1][2 * kt], bhi[1][2 * kt + 1]);
                    mma_bf16(d1 + mt * 4, &ah.x, blo[1][2 * kt], blo[1][2 * kt + 1]);
                }
            }

            // ---- silu in registers ----
            #pragma unroll
            for (int i = 0; i < 16; i++) {
                float x0 = d0[i];
                d0[i] = __fdividef(x0, 1.0f + __expf(-x0));
                float x1 = d1[i];
                d1[i] = __fdividef(x1, 1.0f + __expf(-x1));
            }

            // ---- register transpose via movmatrix: D-frags -> stage-2 A-frags ----
            uint32_t mvh[4][2][2], mvl[4][2][2];   // [kt][g][hh]
            #pragma unroll
            for (int mt = 0; mt < 4; mt++) {
                #pragma unroll
                for (int hh = 0; hh < 2; hh++) {
                    uint32_t h0, l0, h1, l1;
                    split_pack(d0[mt * 4 + 2 * hh], d0[mt * 4 + 2 * hh + 1], h0, l0);
                    split_pack(d1[mt * 4 + 2 * hh], d1[mt * 4 + 2 * hh + 1], h1, l1);
                    mvh[mt][0][hh] = movm(h0);
                    mvl[mt][0][hh] = movm(l0);
                    mvh[mt][1][hh] = movm(h1);
                    mvl[mt][1][hh] = movm(l1);
                }
            }

            // ---- stage-2 MMAs: q[16e,16] = h @ M, 3-term split (M frags from smem) ----
            float q0[4], q1[4];
            #pragma unroll
            for (int i = 0; i < 4; i++) { q0[i] = 0.0f; q1[i] = 0.0f; }
            #pragma unroll
            for (int kt = 0; kt < 4; kt++) {
                uint32_t ah[4] = {mvh[kt][0][0], mvh[kt][1][0], mvh[kt][0][1], mvh[kt][1][1]};
                uint32_t al[4] = {mvl[kt][0][0], mvl[kt][1][0], mvl[kt][0][1], mvl[kt][1][1]};
                uint32_t b0h, b1h, b0l, b1l;
                unpack2u(Mfh[(kt * 2 + 0) * 32 + lane], b0h, b1h);
                unpack2u(Mfl[(kt * 2 + 0) * 32 + lane], b0l, b1l);
                mma_bf16(q0, ah, b0h, b1h);
                mma_bf16(q0, al, b0h, b1h);
                mma_bf16(q0, ah, b0l, b1l);
                unpack2u(Mfh[(kt * 2 + 1) * 32 + lane], b0h, b1h);
                unpack2u(Mfl[(kt * 2 + 1) * 32 + lane], b0l, b1l);
                mma_bf16(q1, ah, b0h, b1h);
                mma_bf16(q1, al, b0h, b1h);
                mma_bf16(q1, ah, b0l, b1l);
            }
            // q layout: (edge m4 [+8], n = 8*nt + 2*j4 + {0,1})

            // ---- s = q . rbf (butterfly over 4-lane n-groups) ----
            int eL0 = min(base16 + m4, N_EDGES - 1);
            int eL1 = min(base16 + m4 + 8, N_EDGES - 1);
            const float2* R0 = (const float2*)(rbf + (size_t)eL0 * EMB_RBF);
            const float2* R1 = (const float2*)(rbf + (size_t)eL1 * EMB_RBF);
            float2 r00 = R0[j4], r01 = R0[4 + j4];
            float2 r10 = R1[j4], r11 = R1[4 + j4];
            float p0 = q0[0] * r00.x + q0[1] * r00.y + q1[0] * r01.x + q1[1] * r01.y;
            float p1 = q0[2] * r10.x + q0[3] * r10.y + q1[2] * r11.x + q1[3] * r11.y;
            p0 += __shfl_xor_sync(0xFFFFFFFFu, p0, 1);
            p0 += __shfl_xor_sync(0xFFFFFFFFu, p0, 2);
            p1 += __shfl_xor_sync(0xFFFFFFFFu, p1, 1);
            p1 += __shfl_xor_sync(0xFFFFFFFFu, p1, 2);

            // ---- geometry + smem histogram (lanes j4<2 each own one edge) ----
            if (j4 < 2) {
                int e = base16 + m4 + 8 * j4;
                if (e < N_EDGES) {
                    float s = j4 ? p1 : p0;
                    int node = load_idx(edge_index, e, is64);
                    node = min(max(node, 0), N_NODES - 1);
                    int g = load_idx(batch, node, is64);
                    g = min(max(g, 0), N_GRAPHS - 1);
                    float dx = distance_vec[3 * e + 0];
                    float dy = distance_vec[3 * e + 1];
                    float dz = distance_vec[3 * e + 2];
                    float coef = s * rsqrtf(dx * dx + dy * dy + dz * dz);
                    float* ag = sAcc + g * 6;
                    atomicAdd(&sCnt[g], 1u);
                    atomicAdd(ag + 0, coef * dx * dx);
                    atomicAdd(ag + 1, coef * dy * dy);
                    atomicAdd(ag + 2, coef * dz * dz);
                    atomicAdd(ag + 3, coef * dx * dy);
                    atomicAdd(ag + 4, coef * dx * dz);
                    atomicAdd(ag + 5, coef * dy * dz);
                }
            }
        }
    }

    // ---- flush per-CTA partials ----
    __syncthreads();
    for (int i = tid; i < N_GRAPHS; i += 128) {
        unsigned int c = sCnt[i];
        if (c) atomicAdd(&g_cnt[i], c);
    }
    for (int i = tid; i < N_GRAPHS * 6; i += 128) {
        float v = sAcc[i];
        if (v != 0.0f) atomicAdd(&g_acc6[i], v);
    }
}

// ---------------- finalize ----------------
__global__ void finalize_kernel(float* __restrict__ out) {
    int g = blockIdx.x * blockDim.x + threadIdx.x;
    if (g >= N_GRAPHS) return;
    unsigned int c = g_cnt[g];
    float inv = c ? (1.0f / (float)c) : 0.0f;
    float xx = g_acc6[g * 6 + 0] * inv;
    float yy = g_acc6[g * 6 + 1] * inv;
    float zz = g_acc6[g * 6 + 2] * inv;
    float xy = g_acc6[g * 6 + 3] * inv;
    float xz = g_acc6[g * 6 + 4] * inv;
    float yz = g_acc6[g * 6 + 5] * inv;
    float* o = out + g * 9;
    o[0] = xx; o[1] = xy; o[2] = xz;
    o[3] = xy; o[4] = yy; o[5] = yz;
    o[6] = xz; o[7] = yz; o[8] = zz;
}

// ---------------- launcher ----------------
extern "C" void kernel_launch(void* const* d_in, const int* in_sizes, int n_in,
                              void* d_out, int out_size) {
    int i_ee = 0, i_ei = 1, i_dv = 2, i_b = 4, i_rbf = 5,
        i_w1 = 6, i_w2 = 7, i_wr = 8, i_wo = 9;
    int seen4096 = 0;
    for (int i = 0; i < n_in; i++) {
        int s = in_sizes[i];
        if      (s == 64000000) i_ee = i;
        else if (s == 2000000)  i_ei = i;
        else if (s == 3000000)  i_dv = i;
        else if (s == 100000)   i_b  = i;
        else if (s == 16000000) i_rbf = i;
        else if (s == 4096)     { if (seen4096++ == 0) i_w1 = i; else i_w2 = i; }
        else if (s == 1024)     i_wr = i;
        else if (s == 64)       i_wo = i;
    }

    const float* edge_emb     = (const float*)d_in[i_ee];
    const void*  edge_index   = d_in[i_ei];
    const float* distance_vec = (const float*)d_in[i_dv];
    const void*  batch        = d_in[i_b];
    const float* rbf          = (const float*)d_in[i_rbf];
    const float* W1           = (const float*)d_in[i_w1];
    const float* W2           = (const float*)d_in[i_w2];
    const float* W_rbf        = (const float*)d_in[i_wr];
    const float* W_out        = (const float*)d_in[i_wo];
    float* out = (float*)d_out;

    setup_kernel<<<1, 1024>>>(W2, W_rbf, W_out, edge_index);
    main_kernel<<<GRID_MAIN, 128>>>(edge_emb, edge_index, distance_vec, batch, rbf, W1);
    finalize_kernel<<<1, 256>>>(out);
    (void)out_size;
}

// round 11
// speedup vs baseline: 4.3544x; 1.3186x over previous
#include <cuda_runtime.h>
#include <cuda_bf16.h>
#include <cstdint>

#define N_GRAPHS 256
#define N_NODES  100000
#define N_EDGES  1000000
#define EMB      64
#define EMB_RBF  16
#define TILE_CTA 128
#define N_TILES  ((N_EDGES + TILE_CTA - 1) / TILE_CTA)  // 7813
#define GRID_MAIN 592

typedef unsigned long long ull;

// ---------------- device scratch ----------------
__device__ float        g_M[EMB * EMB_RBF];    // M[j][k] = sum_m W2[j][m]*Wout[m]*Wrbf[k][m]
__device__ float        g_acc6[N_GRAPHS * 6];
__device__ unsigned int g_cnt[N_GRAPHS];
__device__ int          g_ei64;

// ---------------- helpers ----------------
__device__ __forceinline__ int load_idx(const void* p, int i, int is64) {
    if (is64) return (int)((const long long*)p)[i];
    return ((const int*)p)[i];
}
__device__ __forceinline__ ull pack2u(uint32_t lo, uint32_t hi) {
    ull r; asm("mov.b64 %0, {%1, %2};" : "=l"(r) : "r"(lo), "r"(hi)); return r;
}
__device__ __forceinline__ void unpack2u(ull v, uint32_t& lo, uint32_t& hi) {
    asm("mov.b64 {%0, %1}, %2;" : "=r"(lo), "=r"(hi) : "l"(v));
}

// bf16 hi/lo split of two fp32 -> packed bf16x2 (lower half = first value)
__device__ __forceinline__ void split_pack(float f0, float f1, uint32_t& hi, uint32_t& lo) {
    uint32_t h;
    asm("cvt.rn.bf16x2.f32 %0, %1, %2;" : "=r"(h) : "f"(f1), "f"(f0));
    float r0 = f0 - __uint_as_float(h << 16);
    float r1 = f1 - __uint_as_float(h & 0xFFFF0000u);
    uint32_t l;
    asm("cvt.rn.bf16x2.f32 %0, %1, %2;" : "=r"(l) : "f"(r1), "f"(r0));
    hi = h; lo = l;
}

// silu via single-MUFU tanh: x*sigmoid(x) = 0.5x + 0.5x*tanh(x/2)
__device__ __forceinline__ float silu(float x) {
    float t;
    asm("tanh.approx.f32 %0, %1;" : "=f"(t) : "f"(0.5f * x));
    float hx = 0.5f * x;
    return fmaf(hx, t, hx);
}

__device__ __forceinline__ void mma_bf16(float* d, const uint32_t* a, uint32_t b0, uint32_t b1) {
    asm volatile(
        "mma.sync.aligned.m16n8k16.row.col.f32.bf16.bf16.f32 "
        "{%0,%1,%2,%3}, {%4,%5,%6,%7}, {%8,%9}, {%0,%1,%2,%3};"
        : "+f"(d[0]), "+f"(d[1]), "+f"(d[2]), "+f"(d[3])
        : "r"(a[0]), "r"(a[1]), "r"(a[2]), "r"(a[3]), "r"(b0), "r"(b1));
}

__device__ __forceinline__ uint32_t movm(uint32_t x) {
    uint32_t y;
    asm("movmatrix.sync.aligned.m8n8.trans.b16 %0, %1;" : "=r"(y) : "r"(x));
    return y;
}

// ---------------- setup: distributed detect + zero + fold M (8 blocks) ----------------
__global__ void setup_kernel(const float* __restrict__ W2,
                             const float* __restrict__ Wrbf,
                             const float* __restrict__ Wout,
                             const void*  __restrict__ ei) {
    int b = blockIdx.x, t = threadIdx.x;   // 8 blocks x 256 threads
    if (b < 4) {
        // M entries [b*256, b*256+256)
        int entry = b * 256 + t;
        int j = entry >> 4, k = entry & 15;
        float acc = 0.0f;
        #pragma unroll 8
        for (int m = 0; m < EMB; m++)
            acc += W2[j * EMB + m] * Wout[m] * Wrbf[k * EMB + m];
        g_M[entry] = acc;
    } else if (b == 4) {
        for (int i = t; i < N_GRAPHS * 6; i += 256) g_acc6[i] = 0.0f;
        if (t < N_GRAPHS) g_cnt[t] = 0u;
    } else if (b == 5) {
        __shared__ int nz;
        if (t == 0) nz = 0;
        __syncthreads();
        if (t < 64 && ((const int*)ei)[2 * t + 1] != 0) atomicAdd(&nz, 1);
        __syncthreads();
        if (t == 0) g_ei64 = (nz == 0);
    }
}

// ---------------- main fused kernel ----------------
__global__ void __launch_bounds__(128)
main_kernel(const float* __restrict__ edge_emb,
            const void*  __restrict__ edge_index,
            const float* __restrict__ distance_vec,
            const void*  __restrict__ batch,
            const float* __restrict__ rbf,
            const float* __restrict__ W1) {
    __shared__ uint32_t afh[16 * 32 * 4];     // W1^T hi fragments (8KB)
    __shared__ uint32_t afl[16 * 32 * 4];     // W1^T lo fragments (8KB)
    __shared__ ull      Mfh[8 * 32];          // stage-2 M B-frags hi
    __shared__ ull      Mfl[8 * 32];          // stage-2 M B-frags lo
    __shared__ unsigned int sCnt[N_GRAPHS];
    __shared__ float        sAcc[N_GRAPHS * 6];

    const int tid  = threadIdx.x;
    const int wid  = tid >> 5;
    const int lane = tid & 31;
    const int is64 = g_ei64;
    const int m4 = lane >> 2;      // 0..7
    const int j4 = lane & 3;       // 0..3

    // ---- prologue: A fragments of W1^T (hi/lo) into smem ----
    for (int p = wid; p < 16; p += 4) {
        int mt = p >> 2, kt = p & 3;
        int r0 = 16 * mt + m4;
        int r1 = r0 + 8;
        int k0 = 16 * kt + j4 * 2;
        uint32_t hi[4], lo[4];
        split_pack(W1[(k0    ) * EMB + r0], W1[(k0 + 1) * EMB + r0], hi[0], lo[0]);
        split_pack(W1[(k0    ) * EMB + r1], W1[(k0 + 1) * EMB + r1], hi[1], lo[1]);
        split_pack(W1[(k0 + 8) * EMB + r0], W1[(k0 + 9) * EMB + r0], hi[2], lo[2]);
        split_pack(W1[(k0 + 8) * EMB + r1], W1[(k0 + 9) * EMB + r1], hi[3], lo[3]);
        uint32_t base = (uint32_t)(p * 32 + lane) * 4;
        #pragma unroll
        for (int r = 0; r < 4; r++) { afh[base + r] = hi[r]; afl[base + r] = lo[r]; }
    }
    // ---- stage-2 M fragments into smem ----
    for (int p = wid; p < 8; p += 4) {
        int kt = p >> 1, nt = p & 1;
        int kk = 16 * kt + 2 * j4;
        int n  = 8 * nt + m4;
        uint32_t b0h, b0l, b1h, b1l;
        split_pack(g_M[(kk    ) * EMB_RBF + n], g_M[(kk + 1) * EMB_RBF + n], b0h, b0l);
        split_pack(g_M[(kk + 8) * EMB_RBF + n], g_M[(kk + 9) * EMB_RBF + n], b1h, b1l);
        Mfh[p * 32 + lane] = pack2u(b0h, b1h);
        Mfl[p * 32 + lane] = pack2u(b0l, b1l);
    }
    for (int i = tid; i < N_GRAPHS; i += 128) sCnt[i] = 0u;
    for (int i = tid; i < N_GRAPHS * 6; i += 128) sAcc[i] = 0.0f;
    __syncthreads();

    for (int tile = blockIdx.x; tile < N_TILES; tile += GRID_MAIN) {
        const int base32 = tile * TILE_CTA + wid * 32;
        const int ntile = tile + GRID_MAIN;

        #pragma unroll 1
        for (int pair = 0; pair < 2; pair++) {
            const int base16 = base32 + pair * 16;

            // ---- prefetch next tile's E rows into L2 (1 prefetch/lane) ----
            if (ntile < N_TILES) {
                int pe = ntile * TILE_CTA + wid * 32 + pair * 16 + (lane >> 1);
                pe = min(pe, N_EDGES - 1);
                const float* pf = edge_emb + (size_t)pe * EMB + (lane & 1) * 32;
                asm volatile("prefetch.global.L2 [%0];" :: "l"(pf));
            }

            // ---- stage-1 B fragments: E rows, bf16 hi/lo, 2 edge-subgroups ----
            uint32_t bhi[2][8], blo[2][8];
            #pragma unroll
            for (int g = 0; g < 2; g++) {
                int ec = min(base16 + 8 * g + m4, N_EDGES - 1);
                const float2* Ep = (const float2*)(edge_emb + (size_t)ec * EMB);
                #pragma unroll
                for (int kt = 0; kt < 4; kt++) {
                    float2 x = Ep[j4 + 8 * kt];
                    float2 y = Ep[j4 + 8 * kt + 4];
                    split_pack(x.x, x.y, bhi[g][2 * kt], blo[g][2 * kt]);
                    split_pack(y.x, y.y, bhi[g][2 * kt + 1], blo[g][2 * kt + 1]);
                }
            }

            // ---- stage-1 MMAs: P = E @ W1, 3-term bf16 split, 16 edges ----
            float d0[16], d1[16];
            #pragma unroll
            for (int i = 0; i < 16; i++) { d0[i] = 0.0f; d1[i] = 0.0f; }
            #pragma unroll
            for (int mt = 0; mt < 4; mt++) {
                #pragma unroll
                for (int kt = 0; kt < 4; kt++) {
                    uint4 ah = *(const uint4*)&afh[((mt * 4 + kt) * 32 + lane) * 4];
                    uint4 al = *(const uint4*)&afl[((mt * 4 + kt) * 32 + lane) * 4];
                    mma_bf16(d0 + mt * 4, &ah.x, bhi[0][2 * kt], bhi[0][2 * kt + 1]);
                    mma_bf16(d0 + mt * 4, &al.x, bhi[0][2 * kt], bhi[0][2 * kt + 1]);
                    mma_bf16(d0 + mt * 4, &ah.x, blo[0][2 * kt], blo[0][2 * kt + 1]);
                    mma_bf16(d1 + mt * 4, &ah.x, bhi[1][2 * kt], bhi[1][2 * kt + 1]);
                    mma_bf16(d1 + mt * 4, &al.x, bhi[1][2 * kt], bhi[1][2 * kt + 1]);
                    mma_bf16(d1 + mt * 4, &ah.x, blo[1][2 * kt], blo[1][2 * kt + 1]);
                }
            }

            // ---- silu in registers (single MUFU per element) ----
            #pragma unroll
            for (int i = 0; i < 16; i++) {
                d0[i] = silu(d0[i]);
                d1[i] = silu(d1[i]);
            }

            // ---- register transpose via movmatrix ----
            uint32_t mvh[4][2][2], mvl[4][2][2];   // [kt][g][hh]
            #pragma unroll
            for (int mt = 0; mt < 4; mt++) {
                #pragma unroll
                for (int hh = 0; hh < 2; hh++) {
                    uint32_t h0, l0, h1, l1;
                    split_pack(d0[mt * 4 + 2 * hh], d0[mt * 4 + 2 * hh + 1], h0, l0);
                    split_pack(d1[mt * 4 + 2 * hh], d1[mt * 4 + 2 * hh + 1], h1, l1);
                    mvh[mt][0][hh] = movm(h0);
                    mvl[mt][0][hh] = movm(l0);
                    mvh[mt][1][hh] = movm(h1);
                    mvl[mt][1][hh] = movm(l1);
                }
            }

            // ---- stage-2 MMAs: q[16e,16] = h @ M, 3-term split ----
            float q0[4], q1[4];
            #pragma unroll
            for (int i = 0; i < 4; i++) { q0[i] = 0.0f; q1[i] = 0.0f; }
            #pragma unroll
            for (int kt = 0; kt < 4; kt++) {
                uint32_t ah[4] = {mvh[kt][0][0], mvh[kt][1][0], mvh[kt][0][1], mvh[kt][1][1]};
                uint32_t al[4] = {mvl[kt][0][0], mvl[kt][1][0], mvl[kt][0][1], mvl[kt][1][1]};
                uint32_t b0h, b1h, b0l, b1l;
                unpack2u(Mfh[(kt * 2 + 0) * 32 + lane], b0h, b1h);
                unpack2u(Mfl[(kt * 2 + 0) * 32 + lane], b0l, b1l);
                mma_bf16(q0, ah, b0h, b1h);
                mma_bf16(q0, al, b0h, b1h);
                mma_bf16(q0, ah, b0l, b1l);
                unpack2u(Mfh[(kt * 2 + 1) * 32 + lane], b0h, b1h);
                unpack2u(Mfl[(kt * 2 + 1) * 32 + lane], b0l, b1l);
                mma_bf16(q1, ah, b0h, b1h);
                mma_bf16(q1, al, b0h, b1h);
                mma_bf16(q1, ah, b0l, b1l);
            }

            // ---- s = q . rbf (butterfly over 4-lane n-groups) ----
            int eL0 = min(base16 + m4, N_EDGES - 1);
            int eL1 = min(base16 + m4 + 8, N_EDGES - 1);
            const float2* R0 = (const float2*)(rbf + (size_t)eL0 * EMB_RBF);
            const float2* R1 = (const float2*)(rbf + (size_t)eL1 * EMB_RBF);
            float2 r00 = R0[j4], r01 = R0[4 + j4];
            float2 r10 = R1[j4], r11 = R1[4 + j4];
            float p0 = q0[0] * r00.x + q0[1] * r00.y + q1[0] * r01.x + q1[1] * r01.y;
            float p1 = q0[2] * r10.x + q0[3] * r10.y + q1[2] * r11.x + q1[3] * r11.y;
            p0 += __shfl_xor_sync(0xFFFFFFFFu, p0, 1);
            p0 += __shfl_xor_sync(0xFFFFFFFFu, p0, 2);
            p1 += __shfl_xor_sync(0xFFFFFFFFu, p1, 1);
            p1 += __shfl_xor_sync(0xFFFFFFFFu, p1, 2);

            // ---- geometry + smem histogram ----
            if (j4 < 2) {
                int e = base16 + m4 + 8 * j4;
                if (e < N_EDGES) {
                    float s = j4 ? p1 : p0;
                    int node = load_idx(edge_index, e, is64);
                    node = min(max(node, 0), N_NODES - 1);
                    int g = load_idx(batch, node, is64);
                    g = min(max(g, 0), N_GRAPHS - 1);
                    float dx = distance_vec[3 * e + 0];
                    float dy = distance_vec[3 * e + 1];
                    float dz = distance_vec[3 * e + 2];
                    float coef = s * rsqrtf(dx * dx + dy * dy + dz * dz);
                    float* ag = sAcc + g * 6;
                    atomicAdd(&sCnt[g], 1u);
                    atomicAdd(ag + 0, coef * dx * dx);
                    atomicAdd(ag + 1, coef * dy * dy);
                    atomicAdd(ag + 2, coef * dz * dz);
                    atomicAdd(ag + 3, coef * dx * dy);
                    atomicAdd(ag + 4, coef * dx * dz);
                    atomicAdd(ag + 5, coef * dy * dz);
                }
            }
        }
    }

    // ---- flush per-CTA partials ----
    __syncthreads();
    for (int i = tid; i < N_GRAPHS; i += 128) {
        unsigned int c = sCnt[i];
        if (c) atomicAdd(&g_cnt[i], c);
    }
    for (int i = tid; i < N_GRAPHS * 6; i += 128) {
        float v = sAcc[i];
        if (v != 0.0f) atomicAdd(&g_acc6[i], v);
    }
}

// ---------------- finalize ----------------
__global__ void finalize_kernel(float* __restrict__ out) {
    int g = blockIdx.x * blockDim.x + threadIdx.x;
    if (g >= N_GRAPHS) return;
    unsigned int c = g_cnt[g];
    float inv = c ? (1.0f / (float)c) : 0.0f;
    float xx = g_acc6[g * 6 + 0] * inv;
    float yy = g_acc6[g * 6 + 1] * inv;
    float zz = g_acc6[g * 6 + 2] * inv;
    float xy = g_acc6[g * 6 + 3] * inv;
    float xz = g_acc6[g * 6 + 4] * inv;
    float yz = g_acc6[g * 6 + 5] * inv;
    float* o = out + g * 9;
    o[0] = xx; o[1] = xy; o[2] = xz;
    o[3] = xy; o[4] = yy; o[5] = yz;
    o[6] = xz; o[7] = yz; o[8] = zz;
}

// ---------------- launcher ----------------
extern "C" void kernel_launch(void* const* d_in, const int* in_sizes, int n_in,
                              void* d_out, int out_size) {
    int i_ee = 0, i_ei = 1, i_dv = 2, i_b = 4, i_rbf = 5,
        i_w1 = 6, i_w2 = 7, i_wr = 8, i_wo = 9;
    int seen4096 = 0;
    for (int i = 0; i < n_in; i++) {
        int s = in_sizes[i];
        if      (s == 64000000) i_ee = i;
        else if (s == 2000000)  i_ei = i;
        else if (s == 3000000)  i_dv = i;
        else if (s == 100000)   i_b  = i;
        else if (s == 16000000) i_rbf = i;
        else if (s == 4096)     { if (seen4096++ == 0) i_w1 = i; else i_w2 = i; }
        else if (s == 1024)     i_wr = i;
        else if (s == 64)       i_wo = i;
    }

    const float* edge_emb     = (const float*)d_in[i_ee];
    const void*  edge_index   = d_in[i_ei];
    const float* distance_vec = (const float*)d_in[i_dv];
    const void*  batch        = d_in[i_b];
    const float* rbf          = (const float*)d_in[i_rbf];
    const float* W1           = (const float*)d_in[i_w1];
    const float* W2           = (const float*)d_in[i_w2];
    const float* W_rbf        = (const float*)d_in[i_wr];
    const float* W_out        = (const float*)d_in[i_wo];
    float* out = (float*)d_out;

    setup_kernel<<<8, 256>>>(W2, W_rbf, W_out, edge_index);
    main_kernel<<<GRID_MAIN, 128>>>(edge_emb, edge_index, distance_vec, batch, rbf, W1);
    finalize_kernel<<<1, 256>>>(out);
    (void)out_size;
}

// round 12
// speedup vs baseline: 4.4078x; 1.0123x over previous
#include <cuda_runtime.h>
#include <cstdint>

#define N_GRAPHS 256
#define N_NODES  100000
#define N_EDGES  1000000
#define EMB      64
#define EMB_RBF  16
#define TILE_CTA 128
#define N_TILES  ((N_EDGES + TILE_CTA - 1) / TILE_CTA)  // 7813
#define GRID_MAIN 592

// ---------------- device scratch (zero-initialized at module load; every
// kernel run leaves it zeroed again via the last-CTA reset) ----------------
__device__ float        g_acc6[N_GRAPHS * 6];
__device__ unsigned int g_cnt[N_GRAPHS];
__device__ unsigned int g_done;

// ---------------- helpers ----------------
__device__ __forceinline__ int load_idx(const void* p, int i, int is64) {
    if (is64) return (int)((const long long*)p)[i];
    return ((const int*)p)[i];
}

// bf16 hi/lo split of two fp32 -> packed bf16x2 (lower half = first value)
__device__ __forceinline__ void split_pack(float f0, float f1, uint32_t& hi, uint32_t& lo) {
    uint32_t h;
    asm("cvt.rn.bf16x2.f32 %0, %1, %2;" : "=r"(h) : "f"(f1), "f"(f0));
    float r0 = f0 - __uint_as_float(h << 16);
    float r1 = f1 - __uint_as_float(h & 0xFFFF0000u);
    uint32_t l;
    asm("cvt.rn.bf16x2.f32 %0, %1, %2;" : "=r"(l) : "f"(r1), "f"(r0));
    hi = h; lo = l;
}

// silu via single-MUFU tanh: x*sigmoid(x) = 0.5x + 0.5x*tanh(x/2)
__device__ __forceinline__ float silu(float x) {
    float t;
    asm("tanh.approx.f32 %0, %1;" : "=f"(t) : "f"(0.5f * x));
    float hx = 0.5f * x;
    return fmaf(hx, t, hx);
}

__device__ __forceinline__ void mma_bf16(float* d, const uint32_t* a, uint32_t b0, uint32_t b1) {
    asm volatile(
        "mma.sync.aligned.m16n8k16.row.col.f32.bf16.bf16.f32 "
        "{%0,%1,%2,%3}, {%4,%5,%6,%7}, {%8,%9}, {%0,%1,%2,%3};"
        : "+f"(d[0]), "+f"(d[1]), "+f"(d[2]), "+f"(d[3])
        : "r"(a[0]), "r"(a[1]), "r"(a[2]), "r"(a[3]), "r"(b0), "r"(b1));
}

// ---------------- the single fused kernel ----------------
__global__ void __launch_bounds__(128)
main_kernel(const float* __restrict__ edge_emb,
            const void*  __restrict__ edge_index,
            const float* __restrict__ distance_vec,
            const void*  __restrict__ batch,
            const float* __restrict__ rbf,
            const float* __restrict__ W1,
            const float* __restrict__ W2,
            const float* __restrict__ Wrbf,
            const float* __restrict__ Wout,
            float* __restrict__ out) {
    __shared__ uint32_t afh[2048];          // W1^T hi fragments (8KB)
    __shared__ uint32_t afl[2048];          // W1^T lo fragments (8KB); scratch for M entries first
    __shared__ uint32_t afM[1024];          // M A-frags: hi at [mt*128+lane*4+r], lo at +512 (4KB)
    __shared__ unsigned int sCnt[N_GRAPHS];
    __shared__ float        sAcc[N_GRAPHS * 6];   // scratch for T first
    __shared__ int sFlag[2];                // [0]=is64, [1]=isLastCTA

    const int tid  = threadIdx.x;
    const int wid  = tid >> 5;
    const int lane = tid & 31;
    const int m4 = lane >> 2;      // 0..7
    const int j4 = lane & 3;       // 0..3

    // ---- dtype detect (warp 0): int64 iff all 64 leading odd words are 0 ----
    if (wid == 0) {
        const int* p = (const int*)edge_index;
        int nz = (p[2 * lane + 1] != 0) | (p[2 * (lane + 32) + 1] != 0);
        unsigned b = __ballot_sync(0xFFFFFFFFu, nz);
        if (lane == 0) sFlag[0] = (b == 0);
    }

    // ---- T[k][m] = Wout[m] * Wrbf[k][m] into sAcc scratch ----
    for (int i = tid; i < EMB_RBF * EMB; i += 128) {
        int k = i >> 6, m = i & 63;
        sAcc[i] = Wout[m] * Wrbf[k * EMB + m];
    }
    __syncthreads();
    const int is64 = sFlag[0];

    // ---- M[j][k] = sum_m W2[j][m] * T[k][m] into Mtmp (= afl scratch) ----
    {
        float* Mtmp = (float*)afl;
        int j = tid >> 1;
        int kbase = (tid & 1) * 8;
        const float4* W2r = (const float4*)(W2 + j * EMB);
        float acc[8];
        #pragma unroll
        for (int kk = 0; kk < 8; kk++) acc[kk] = 0.0f;
        #pragma unroll 4
        for (int mc = 0; mc < 16; mc++) {
            float4 wv = W2r[mc];
            int m = mc * 4;
            #pragma unroll
            for (int kk = 0; kk < 8; kk++) {
                const float* Tr = sAcc + (kbase + kk) * EMB + m;
                acc[kk] += wv.x * Tr[0] + wv.y * Tr[1] + wv.z * Tr[2] + wv.w * Tr[3];
            }
        }
        #pragma unroll
        for (int kk = 0; kk < 8; kk++) Mtmp[j * EMB_RBF + kbase + kk] = acc[kk];
    }
    __syncthreads();

    // ---- build M A-fragments (warp wid = mt tile) ----
    {
        const float* Mtmp = (const float*)afl;
        int r0 = 16 * wid + m4;
        int k0 = 2 * j4;
        uint32_t h, l;
        split_pack(Mtmp[r0 * EMB_RBF + k0],           Mtmp[r0 * EMB_RBF + k0 + 1],           h, l);
        afM[wid * 128 + lane * 4 + 0] = h; afM[512 + wid * 128 + lane * 4 + 0] = l;
        split_pack(Mtmp[(r0 + 8) * EMB_RBF + k0],     Mtmp[(r0 + 8) * EMB_RBF + k0 + 1],     h, l);
        afM[wid * 128 + lane * 4 + 1] = h; afM[512 + wid * 128 + lane * 4 + 1] = l;
        split_pack(Mtmp[r0 * EMB_RBF + k0 + 8],       Mtmp[r0 * EMB_RBF + k0 + 9],           h, l);
        afM[wid * 128 + lane * 4 + 2] = h; afM[512 + wid * 128 + lane * 4 + 2] = l;
        split_pack(Mtmp[(r0 + 8) * EMB_RBF + k0 + 8], Mtmp[(r0 + 8) * EMB_RBF + k0 + 9],     h, l);
        afM[wid * 128 + lane * 4 + 3] = h; afM[512 + wid * 128 + lane * 4 + 3] = l;
    }
    __syncthreads();

    // ---- W1^T A-fragments (hi/lo) into afh/afl; zero histograms ----
    for (int p = wid; p < 16; p += 4) {
        int mt = p >> 2, kt = p & 3;
        int r0 = 16 * mt + m4;
        int r1 = r0 + 8;
        int k0 = 16 * kt + j4 * 2;
        uint32_t hi[4], lo[4];
        split_pack(W1[(k0    ) * EMB + r0], W1[(k0 + 1) * EMB + r0], hi[0], lo[0]);
        split_pack(W1[(k0    ) * EMB + r1], W1[(k0 + 1) * EMB + r1], hi[1], lo[1]);
        split_pack(W1[(k0 + 8) * EMB + r0], W1[(k0 + 9) * EMB + r0], hi[2], lo[2]);
        split_pack(W1[(k0 + 8) * EMB + r1], W1[(k0 + 9) * EMB + r1], hi[3], lo[3]);
        uint32_t base = (uint32_t)(p * 32 + lane) * 4;
        #pragma unroll
        for (int r = 0; r < 4; r++) { afh[base + r] = hi[r]; afl[base + r] = lo[r]; }
    }
    for (int i = tid; i < N_GRAPHS; i += 128) sCnt[i] = 0u;
    for (int i = tid; i < N_GRAPHS * 6; i += 128) sAcc[i] = 0.0f;
    __syncthreads();

    // ================= main loop =================
    for (int tile = blockIdx.x; tile < N_TILES; tile += GRID_MAIN) {
        const int base32 = tile * TILE_CTA + wid * 32;
        const int ntile = tile + GRID_MAIN;

        #pragma unroll 1
        for (int pair = 0; pair < 2; pair++) {
            const int base16 = base32 + pair * 16;

            // ---- L2 prefetch next tile (E rows + rbf rows) ----
            if (ntile < N_TILES) {
                int nb = ntile * TILE_CTA + wid * 32 + pair * 16;
                int pe = min(nb + (lane >> 1), N_EDGES - 1);
                const float* pf = edge_emb + (size_t)pe * EMB + (lane & 1) * 32;
                asm volatile("prefetch.global.L2 [%0];" :: "l"(pf));
                if (lane < 8) {
                    const float* pr = rbf + (size_t)min(nb, N_EDGES - 16) * EMB_RBF + lane * 32;
                    asm volatile("prefetch.global.L2 [%0];" :: "l"(pr));
                }
            }

            // ---- stage-1 B fragments: E rows, bf16 hi/lo, 2 edge-subgroups ----
            uint32_t bhi[2][8], blo[2][8];
            #pragma unroll
            for (int g = 0; g < 2; g++) {
                int ec = min(base16 + 8 * g + m4, N_EDGES - 1);
                const float2* Ep = (const float2*)(edge_emb + (size_t)ec * EMB);
                #pragma unroll
                for (int kt = 0; kt < 4; kt++) {
                    float2 x = Ep[j4 + 8 * kt];
                    float2 y = Ep[j4 + 8 * kt + 4];
                    split_pack(x.x, x.y, bhi[g][2 * kt], blo[g][2 * kt]);
                    split_pack(y.x, y.y, bhi[g][2 * kt + 1], blo[g][2 * kt + 1]);
                }
            }

            // ---- stage-1 MMAs: P = E @ W1, 3-term bf16 split, 16 edges ----
            float h0[16], h1[16];
            #pragma unroll
            for (int i = 0; i < 16; i++) { h0[i] = 0.0f; h1[i] = 0.0f; }
            #pragma unroll
            for (int mt = 0; mt < 4; mt++) {
                #pragma unroll
                for (int kt = 0; kt < 4; kt++) {
                    uint4 ah = *(const uint4*)&afh[((mt * 4 + kt) * 32 + lane) * 4];
                    uint4 al = *(const uint4*)&afl[((mt * 4 + kt) * 32 + lane) * 4];
                    mma_bf16(h0 + mt * 4, &ah.x, bhi[0][2 * kt], bhi[0][2 * kt + 1]);
                    mma_bf16(h0 + mt * 4, &al.x, bhi[0][2 * kt], bhi[0][2 * kt + 1]);
                    mma_bf16(h0 + mt * 4, &ah.x, blo[0][2 * kt], blo[0][2 * kt + 1]);
                    mma_bf16(h1 + mt * 4, &ah.x, bhi[1][2 * kt], bhi[1][2 * kt + 1]);
                    mma_bf16(h1 + mt * 4, &al.x, bhi[1][2 * kt], bhi[1][2 * kt + 1]);
                    mma_bf16(h1 + mt * 4, &ah.x, blo[1][2 * kt], blo[1][2 * kt + 1]);
                }
            }

            // ---- silu in fp32 (stays fp32 — no re-split) ----
            #pragma unroll
            for (int i = 0; i < 16; i++) {
                h0[i] = silu(h0[i]);
                h1[i] = silu(h1[i]);
            }

            // ---- V = M @ rbf^T : same fragment layout as h ----
            uint32_t rbh[2][2], rbl[2][2];
            #pragma unroll
            for (int g = 0; g < 2; g++) {
                int ec = min(base16 + 8 * g + m4, N_EDGES - 1);
                const float2* R = (const float2*)(rbf + (size_t)ec * EMB_RBF);
                float2 x = R[j4], y = R[4 + j4];
                split_pack(x.x, x.y, rbh[g][0], rbl[g][0]);
                split_pack(y.x, y.y, rbh[g][1], rbl[g][1]);
            }
            float v0[16], v1[16];
            #pragma unroll
            for (int i = 0; i < 16; i++) { v0[i] = 0.0f; v1[i] = 0.0f; }
            #pragma unroll
            for (int mt = 0; mt < 4; mt++) {
                uint4 mh = *(const uint4*)&afM[mt * 128 + lane * 4];
                uint4 ml = *(const uint4*)&afM[512 + mt * 128 + lane * 4];
                mma_bf16(v0 + mt * 4, &mh.x, rbh[0][0], rbh[0][1]);
                mma_bf16(v0 + mt * 4, &ml.x, rbh[0][0], rbh[0][1]);
                mma_bf16(v0 + mt * 4, &mh.x, rbl[0][0], rbl[0][1]);
                mma_bf16(v1 + mt * 4, &mh.x, rbh[1][0], rbh[1][1]);
                mma_bf16(v1 + mt * 4, &ml.x, rbh[1][0], rbh[1][1]);
                mma_bf16(v1 + mt * 4, &mh.x, rbl[1][0], rbl[1][1]);
            }

            // ---- s = sum_f h*v : elementwise + butterfly over m4 lanes ----
            float acc[4] = {0.0f, 0.0f, 0.0f, 0.0f};   // [g*2 + b]
            #pragma unroll
            for (int mt = 0; mt < 4; mt++) {
                #pragma unroll
                for (int i = 0; i < 4; i++) {
                    acc[i & 1]       = fmaf(h0[mt * 4 + i], v0[mt * 4 + i], acc[i & 1]);
                    acc[2 + (i & 1)] = fmaf(h1[mt * 4 + i], v1[mt * 4 + i], acc[2 + (i & 1)]);
                }
            }
            #pragma unroll
            for (int k = 4; k <= 16; k <<= 1) {
                #pragma unroll
                for (int j = 0; j < 4; j++)
                    acc[j] += __shfl_xor_sync(0xFFFFFFFFu, acc[j], k);
            }

            // ---- geometry + smem histogram (16 active lanes: m4 < 4) ----
            if (m4 < 4) {
                int gg = m4 >> 1, b = m4 & 1;
                int e = base16 + 8 * gg + 2 * j4 + b;
                if (e < N_EDGES) {
                    float s = acc[m4];
                    int node = load_idx(edge_index, e, is64);
                    node = min(max(node, 0), N_NODES - 1);
                    int g = load_idx(batch, node, is64);
                    g = min(max(g, 0), N_GRAPHS - 1);
                    float dx = distance_vec[3 * e + 0];
                    float dy = distance_vec[3 * e + 1];
                    float dz = distance_vec[3 * e + 2];
                    float coef = s * rsqrtf(dx * dx + dy * dy + dz * dz);
                    float* ag = sAcc + g * 6;
                    atomicAdd(&sCnt[g], 1u);
                    atomicAdd(ag + 0, coef * dx * dx);
                    atomicAdd(ag + 1, coef * dy * dy);
                    atomicAdd(ag + 2, coef * dz * dz);
                    atomicAdd(ag + 3, coef * dx * dy);
                    atomicAdd(ag + 4, coef * dx * dz);
                    atomicAdd(ag + 5, coef * dy * dz);
                }
            }
        }
    }

    // ---- flush per-CTA partials ----
    __syncthreads();
    for (int i = tid; i < N_GRAPHS; i += 128) {
        unsigned int c = sCnt[i];
        if (c) atomicAdd(&g_cnt[i], c);
    }
    for (int i = tid; i < N_GRAPHS * 6; i += 128) {
        float v = sAcc[i];
        if (v != 0.0f) atomicAdd(&g_acc6[i], v);
    }
    __threadfence();
    __syncthreads();

    // ---- last CTA finalizes and re-zeroes global scratch ----
    if (tid == 0) {
        unsigned int v = atomicAdd(&g_done, 1u);
        sFlag[1] = (v == (unsigned int)(gridDim.x - 1));
    }
    __syncthreads();
    if (sFlag[1]) {
        for (int g = tid; g < N_GRAPHS; g += 128) {
            unsigned int c = *((volatile unsigned int*)&g_cnt[g]);
            float inv = c ? (1.0f / (float)c) : 0.0f;
            float xx = __ldcg(&g_acc6[g * 6 + 0]) * inv;
            float yy = __ldcg(&g_acc6[g * 6 + 1]) * inv;
            float zz = __ldcg(&g_acc6[g * 6 + 2]) * inv;
            float xy = __ldcg(&g_acc6[g * 6 + 3]) * inv;
            float xz = __ldcg(&g_acc6[g * 6 + 4]) * inv;
            float yz = __ldcg(&g_acc6[g * 6 + 5]) * inv;
            float* o = out + g * 9;
            o[0] = xx; o[1] = xy; o[2] = xz;
            o[3] = xy; o[4] = yy; o[5] = yz;
            o[6] = xz; o[7] = yz; o[8] = zz;
            g_cnt[g] = 0u;
            #pragma unroll
            for (int i = 0; i < 6; i++) g_acc6[g * 6 + i] = 0.0f;
        }
        if (tid == 0) g_done = 0u;
    }
}

// ---------------- launcher: ONE kernel ----------------
extern "C" void kernel_launch(void* const* d_in, const int* in_sizes, int n_in,
                              void* d_out, int out_size) {
    int i_ee = 0, i_ei = 1, i_dv = 2, i_b = 4, i_rbf = 5,
        i_w1 = 6, i_w2 = 7, i_wr = 8, i_wo = 9;
    int seen4096 = 0;
    for (int i = 0; i < n_in; i++) {
        int s = in_sizes[i];
        if      (s == 64000000) i_ee = i;
        else if (s == 2000000)  i_ei = i;
        else if (s == 3000000)  i_dv = i;
        else if (s == 100000)   i_b  = i;
        else if (s == 16000000) i_rbf = i;
        else if (s == 4096)     { if (seen4096++ == 0) i_w1 = i; else i_w2 = i; }
        else if (s == 1024)     i_wr = i;
        else if (s == 64)       i_wo = i;
    }

    main_kernel<<<GRID_MAIN, 128>>>(
        (const float*)d_in[i_ee], d_in[i_ei], (const float*)d_in[i_dv],
        d_in[i_b], (const float*)d_in[i_rbf], (const float*)d_in[i_w1],
        (const float*)d_in[i_w2], (const float*)d_in[i_wr], (const float*)d_in[i_wo],
        (float*)d_out);
    (void)out_size;
}